// round 13
// baseline (speedup 1.0000x reference)
#include <cuda_runtime.h>
#include <cuda_fp16.h>
#include <cstdint>

// ---------------------------------------------------------------------------
// LoRARowParallelLinear, mma.sync fp16 m16n8k16 (compute_103-safe).
// SINGLE fused kernel, 2304 blocks:
//   [0,128)    conv: x/W/lora_A -> fp16 frags in 16 k-groups (+Bcat in grp 0),
//              publishing g_done[grp] (release).
//   [128,256)  lora: u = mask*scal*(x @ lora_A^T) -> g_uh; gated per-group on
//              g_done; releases g_flag when its u slice is visible.
//   [256,2304) main: y = x@W^T (K=4096) + u@Bcat^T (K-ext) + bias; gated
//              per-group on g_done, and on g_flag before the K-ext window.
// main config: CTA 128x128, 4 warps (64x64 warp tile), 6 stages, occ 2,
// barrier every 3 iterations, .cg (L2-only) staging.
// Counters reset by last-exiting block (g_exit ticket) -> replay-safe.
// ---------------------------------------------------------------------------

#define DEVINL static __device__ __forceinline__

namespace {
constexpr int TOK = 8192, DIN = 4096, DOUT = 4096;
constexpr int KB16 = DIN / 16;   // 256 k16-blocks
constexpr int NTI  = 132;        // 128 main BK32 iters + 4 K-ext iters (= 44*3)
constexpr int NCONV = 128, NLORA = 128, NMAIN = 2048;
constexpr int GRID  = NCONV + NLORA + NMAIN;  // 2304
}

// scratch (allocation-free __device__ globals)
__device__ __align__(128) uint32_t g_xh  [(TOK / 16) * KB16 * 128];  // 67 MB
__device__ __align__(128) uint32_t g_wh  [(DOUT / 8) * KB16 * 64];   // 33.5 MB
__device__ __align__(128) uint32_t g_lah [16 * KB16 * 64];           // 1 MB
__device__ __align__(128) uint32_t g_bcat[(DOUT / 8) * 8 * 64];      // 1 MB
__device__ __align__(128) uint32_t g_uh  [(TOK / 16) * 8 * 128];     // 2 MB
__device__ int g_done[16];   // conv blocks finished per k-group (zero-init)
__device__ int g_flag;       // lora blocks finished (zero-init)
__device__ int g_exit;       // exit ticket (zero-init)

DEVINL uint32_t h2pack(float lo, float hi) {
    __half2 h = __float22half2_rn(make_float2(lo, hi));
    return *reinterpret_cast<uint32_t*>(&h);
}

DEVINL void mma_f16(float& d0, float& d1, float& d2, float& d3,
                    uint32_t a0, uint32_t a1, uint32_t a2, uint32_t a3,
                    uint32_t b0, uint32_t b1)
{
    asm volatile(
        "mma.sync.aligned.m16n8k16.row.col.f32.f16.f16.f32 "
        "{%0,%1,%2,%3},{%4,%5,%6,%7},{%8,%9},{%0,%1,%2,%3};"
        : "+f"(d0), "+f"(d1), "+f"(d2), "+f"(d3)
        : "r"(a0), "r"(a1), "r"(a2), "r"(a3), "r"(b0), "r"(b1));
}

DEVINL void cpa16(const uint32_t* smem_dst, const void* gsrc) {
    uint32_t s = (uint32_t)__cvta_generic_to_shared(smem_dst);
    asm volatile("cp.async.cg.shared.global [%0], [%1], 16;" :: "r"(s), "l"(gsrc));
}
DEVINL void cpcommit() { asm volatile("cp.async.commit_group;"); }
template <int N> DEVINL void cpwait() { asm volatile("cp.async.wait_group %0;" :: "n"(N)); }
DEVINL int ld_acq(const int* p) {
    int v;
    asm volatile("ld.acquire.gpu.global.b32 %0, [%1];" : "=r"(v) : "l"(p) : "memory");
    return v;
}

// ---------------------------------------------------------------------------
__global__ void __launch_bounds__(128, 2) fused_kernel(
    const float* __restrict__ x, const float* __restrict__ w,
    const float* __restrict__ la, const float* __restrict__ lb,
    const int* __restrict__ t2s, const float* __restrict__ scal,
    float* __restrict__ C, const float* __restrict__ bias)
{
    extern __shared__ uint32_t sm[];
    const int tid = threadIdx.x, lane = tid & 31, warp = tid >> 5;
    const int wm = warp >> 1, wn = warp & 1;

    if (blockIdx.x < NCONV) {
        // ================= conv blocks =================
        float* cs = reinterpret_cast<float*>(sm) + warp * (16 * 36);
        const int wg = blockIdx.x * 4 + warp;    // 0..511
        const int gl = lane >> 2;
        const int k0 = (lane & 3) * 2;

        for (int grp = 0; grp < 16; grp++) {
            for (int t = wg; t < 8320; t += 512) {
                if (t < 4096) {
                    // x superblock: 16 rows x 32 cols -> g_xh A-frags
                    const int mt = t >> 3, kt2 = grp * 8 + (t & 7);
                    const int r = lane >> 1, coff = (lane & 1) * 16;
                    const float* base = x + (size_t)(mt * 16) * DIN + kt2 * 32;
                    #pragma unroll
                    for (int q = 0; q < 4; q++)
                        *reinterpret_cast<float4*>(cs + r * 36 + coff + q * 4) =
                            *reinterpret_cast<const float4*>(base + (size_t)r * DIN + coff + q * 4);
                    __syncwarp();
                    #pragma unroll
                    for (int kb = 0; kb < 2; kb++) {
                        const int K = kb * 16;
                        uint4 v;
                        v.x = h2pack(cs[gl * 36 + K + k0],           cs[gl * 36 + K + k0 + 1]);
                        v.y = h2pack(cs[(gl + 8) * 36 + K + k0],     cs[(gl + 8) * 36 + K + k0 + 1]);
                        v.z = h2pack(cs[gl * 36 + K + k0 + 8],       cs[gl * 36 + K + k0 + 9]);
                        v.w = h2pack(cs[(gl + 8) * 36 + K + k0 + 8], cs[(gl + 8) * 36 + K + k0 + 9]);
                        *reinterpret_cast<uint4*>(
                            g_xh + ((size_t)mt * KB16 + kt2 * 2 + kb) * 128 + lane * 4) = v;
                    }
                    __syncwarp();
                } else if (t < 8192) {
                    // W superblock: 8 rows x 32 cols -> g_wh B-frags
                    const int nt = (t - 4096) >> 3, kt2 = grp * 8 + (t & 7);
                    const int r = lane >> 2, coff = (lane & 3) * 8;
                    const float* base = w + (size_t)(nt * 8) * DIN + kt2 * 32;
                    #pragma unroll
                    for (int q = 0; q < 2; q++)
                        *reinterpret_cast<float4*>(cs + r * 36 + coff + q * 4) =
                            *reinterpret_cast<const float4*>(base + (size_t)r * DIN + coff + q * 4);
                    __syncwarp();
                    #pragma unroll
                    for (int kb = 0; kb < 2; kb++) {
                        const int K = kb * 16;
                        uint2 v;
                        v.x = h2pack(cs[gl * 36 + K + k0],     cs[gl * 36 + K + k0 + 1]);
                        v.y = h2pack(cs[gl * 36 + K + k0 + 8], cs[gl * 36 + K + k0 + 9]);
                        *reinterpret_cast<uint2*>(
                            g_wh + ((size_t)nt * KB16 + kt2 * 2 + kb) * 64 + lane * 2) = v;
                    }
                    __syncwarp();
                } else {
                    // lora_A superblock: 8 rows x 32 cols -> g_lah B-frags
                    const int nt = (t - 8192) >> 3, kt2 = grp * 8 + (t & 7);
                    const int r = lane >> 2, coff = (lane & 3) * 8;
                    const float* base = la + (size_t)(nt * 8) * DIN + kt2 * 32;
                    #pragma unroll
                    for (int q = 0; q < 2; q++)
                        *reinterpret_cast<float4*>(cs + r * 36 + coff + q * 4) =
                            *reinterpret_cast<const float4*>(base + (size_t)r * DIN + coff + q * 4);
                    __syncwarp();
                    #pragma unroll
                    for (int kb = 0; kb < 2; kb++) {
                        const int K = kb * 16;
                        uint2 v;
                        v.x = h2pack(cs[gl * 36 + K + k0],     cs[gl * 36 + K + k0 + 1]);
                        v.y = h2pack(cs[gl * 36 + K + k0 + 8], cs[gl * 36 + K + k0 + 9]);
                        *reinterpret_cast<uint2*>(
                            g_lah + ((size_t)nt * KB16 + kt2 * 2 + kb) * 64 + lane * 2) = v;
                    }
                    __syncwarp();
                }
            }
            if (grp == 0) {
                // Bcat: lora_B [8][DOUT][16] -> g_bcat: Bcat[n][s*16+r]=lB[s][n][r]
                for (int i = blockIdx.x * 128 + tid; i < DOUT * 64; i += NCONV * 128) {
                    const int n = i >> 6, p = i & 63;
                    const int kc = p * 2;
                    const int sl = kc >> 4, rr = kc & 15;
                    const float f0 = lb[(size_t)sl * DOUT * 16 + n * 16 + rr];
                    const float f1 = lb[(size_t)sl * DOUT * 16 + n * 16 + rr + 1];
                    const int nt = n >> 3, gg = n & 7;
                    const int kbb  = kc >> 4;
                    const int lpos = gg * 4 + ((kc & 7) >> 1);
                    const int word = lpos * 2 + ((kc >> 3) & 1);
                    g_bcat[((size_t)nt * 8 + kbb) * 64 + word] = h2pack(f0, f1);
                }
            }
            __syncthreads();
            if (tid == 0) { __threadfence(); atomicAdd(&g_done[grp], 1); }
        }
    } else if (blockIdx.x < NCONV + NLORA) {
        // ================= lora blocks =================
        constexpr int A_ST = 1024, B_ST = 2048, STW = A_ST + B_ST;  // words
        const int bm = blockIdx.x - NCONV;

        float acc[2][8][4];
        #pragma unroll
        for (int i = 0; i < 2; i++)
            #pragma unroll
            for (int j = 0; j < 8; j++)
                #pragma unroll
                for (int k = 0; k < 4; k++) acc[i][j][k] = 0.f;

        auto load_stage = [&](int f, int buf) {
            uint32_t* sA = sm + buf * STW;
            uint32_t* sB = sA + A_ST;
            #pragma unroll
            for (int q = tid; q < 256; q += 128) {
                const int mt = q >> 6, kb = (q >> 5) & 1, c = q & 31;
                cpa16(sA + (mt * 2 + kb) * 128 + c * 4,
                      g_xh + ((size_t)(bm * 4 + mt) * KB16 + f * 2 + kb) * 128 + c * 4);
            }
            #pragma unroll
            for (int q = tid; q < 512; q += 128) {
                const int nt = q >> 5, kb = (q >> 4) & 1, c = q & 15;
                cpa16(sB + (nt * 2 + kb) * 64 + c * 4,
                      g_lah + ((size_t)nt * KB16 + f * 2 + kb) * 64 + c * 4);
            }
        };

        // gate group 0, then prologue
        if (tid == 0) while (ld_acq(&g_done[0]) < NCONV) {}
        __syncthreads();
        int gotG = 0;

        load_stage(0, 0); cpcommit();
        load_stage(1, 1); cpcommit();
        load_stage(2, 2); cpcommit();

        for (int ci = 0; ci < 128; ci++) {
            const int fmax = (ci + 3 < 128) ? (ci + 3) : 127;
            const int G = fmax >> 3;
            if (G > gotG) {
                if (tid == 0) while (ld_acq(&g_done[G]) < NCONV) {}
                __syncthreads();
                gotG = G;
            }
            cpwait<2>();
            __syncthreads();
            if (ci + 3 < 128) load_stage(ci + 3, (ci + 3) & 3);
            cpcommit();

            const uint32_t* sA = sm + (ci & 3) * STW;
            const uint32_t* sB = sA + A_ST;
            const uint32_t* aw = sA + (wm * 2) * 2 * 128 + lane * 4;
            const uint32_t* bw = sB + (wn * 8) * 2 * 64 + lane * 2;

            #pragma unroll
            for (int kb = 0; kb < 2; kb++) {
                uint4 a[2];
                a[0] = *reinterpret_cast<const uint4*>(aw + kb * 128);
                a[1] = *reinterpret_cast<const uint4*>(aw + (2 + kb) * 128);
                uint2 b[8];
                #pragma unroll
                for (int j = 0; j < 8; j++)
                    b[j] = *reinterpret_cast<const uint2*>(bw + (j * 2 + kb) * 64);
                #pragma unroll
                for (int i = 0; i < 2; i++)
                    #pragma unroll
                    for (int j = 0; j < 8; j++)
                        mma_f16(acc[i][j][0], acc[i][j][1], acc[i][j][2], acc[i][j][3],
                                a[i].x, a[i].y, a[i].z, a[i].w, b[j].x, b[j].y);
            }
        }

        // epilogue: mask*scale -> g_uh fp16 A-frag blocks
        #pragma unroll
        for (int i = 0; i < 2; i++) {
            const int mrow0 = bm * 64 + wm * 32 + i * 16 + (lane >> 2);
            const int slot0 = t2s[mrow0];
            const int slot1 = t2s[mrow0 + 8];
            const float sc0 = scal[slot0];
            const float sc1 = scal[slot1];
            const int mt = bm * 4 + wm * 2 + i;
            #pragma unroll
            for (int j = 0; j < 8; j += 2) {
                const int kbg = wn * 4 + (j >> 1);
                const int n0 = wn * 64 + j * 8 + (lane & 3) * 2;
                const int n1 = n0 + 8;
                const float m00 = ((n0 >> 4) == slot0) ? sc0 : 0.f;
                const float m01 = ((n0 >> 4) == slot1) ? sc1 : 0.f;
                const float m10 = ((n1 >> 4) == slot0) ? sc0 : 0.f;
                const float m11 = ((n1 >> 4) == slot1) ? sc1 : 0.f;
                uint4 v;
                v.x = h2pack(acc[i][j][0] * m00,     acc[i][j][1] * m00);
                v.y = h2pack(acc[i][j][2] * m01,     acc[i][j][3] * m01);
                v.z = h2pack(acc[i][j + 1][0] * m10, acc[i][j + 1][1] * m10);
                v.w = h2pack(acc[i][j + 1][2] * m11, acc[i][j + 1][3] * m11);
                *reinterpret_cast<uint4*>(g_uh + ((size_t)mt * 8 + kbg) * 128 + lane * 4) = v;
            }
        }

        __threadfence();
        __syncthreads();
        if (tid == 0) atomicAdd(&g_flag, 1);
    } else {
        // ================= main blocks =================
        constexpr int A_ST = 2048, B_ST = 2048, STW = A_ST + B_ST;  // words/stage
        const int mid = blockIdx.x - (NCONV + NLORA);
        const int bn = mid & 31, bm = mid >> 5;

        float acc[4][8][4];
        #pragma unroll
        for (int i = 0; i < 4; i++)
            #pragma unroll
            for (int j = 0; j < 8; j++)
                #pragma unroll
                for (int k = 0; k < 4; k++) acc[i][j][k] = 0.f;

        auto load_stage = [&](int f, int buf) {
            uint32_t* sA = sm + buf * STW;
            uint32_t* sB = sA + A_ST;
            #pragma unroll
            for (int q = tid; q < 512; q += 128) {
                const int mt = q >> 6, kb = (q >> 5) & 1, c = q & 31;
                const uint32_t* src = (f < 128)
                    ? g_xh + ((size_t)(bm * 8 + mt) * KB16 + f * 2 + kb) * 128 + c * 4
                    : g_uh + ((size_t)(bm * 8 + mt) * 8 + (f - 128) * 2 + kb) * 128 + c * 4;
                cpa16(sA + (mt * 2 + kb) * 128 + c * 4, src);
            }
            #pragma unroll
            for (int q = tid; q < 512; q += 128) {
                const int nt = q >> 5, kb = (q >> 4) & 1, c = q & 15;
                const uint32_t* src = (f < 128)
                    ? g_wh   + ((size_t)(bn * 16 + nt) * KB16 + f * 2 + kb) * 64 + c * 4
                    : g_bcat + ((size_t)(bn * 16 + nt) * 8 + (f - 128) * 2 + kb) * 64 + c * 4;
                cpa16(sB + (nt * 2 + kb) * 64 + c * 4, src);
            }
        };

        auto compute = [&](int ci) {
            const uint32_t* sA = sm + (ci % 6) * STW;
            const uint32_t* sB = sA + A_ST;
            const uint32_t* aw = sA + (wm * 4) * 2 * 128 + lane * 4;
            const uint32_t* bw = sB + (wn * 8) * 2 * 64 + lane * 2;
            #pragma unroll
            for (int kb = 0; kb < 2; kb++) {
                uint4 a[4];
                #pragma unroll
                for (int i = 0; i < 4; i++)
                    a[i] = *reinterpret_cast<const uint4*>(aw + (i * 2 + kb) * 128);
                uint2 b[8];
                #pragma unroll
                for (int j = 0; j < 8; j++)
                    b[j] = *reinterpret_cast<const uint2*>(bw + (j * 2 + kb) * 64);
                #pragma unroll
                for (int i = 0; i < 4; i++)
                    #pragma unroll
                    for (int j = 0; j < 8; j++)
                        mma_f16(acc[i][j][0], acc[i][j][1], acc[i][j][2], acc[i][j][3],
                                a[i].x, a[i].y, a[i].z, a[i].w, b[j].x, b[j].y);
            }
        };

        auto window = [&](int ci) {
            cpwait<2>();
            __syncthreads();
            if (ci + 3 < NTI) load_stage(ci + 3, (ci + 3) % 6);
            cpcommit();
            compute(ci);
            cpwait<2>();
            if (ci + 4 < NTI) load_stage(ci + 4, (ci + 4) % 6);
            cpcommit();
            compute(ci + 1);
            cpwait<2>();
            if (ci + 5 < NTI) load_stage(ci + 5, (ci + 5) % 6);
            cpcommit();
            compute(ci + 2);
        };

        // gate group 0, then prologue
        if (tid == 0) while (ld_acq(&g_done[0]) < NCONV) {}
        __syncthreads();
        int gotG = 0;

        load_stage(0, 0); cpcommit();
        load_stage(1, 1); cpcommit();
        load_stage(2, 2); cpcommit();

        // windows 0..120: fills f <= 125 (< 128); gate conv group (ci+5)>>3
        for (int ci = 0; ci < 123; ci += 3) {
            const int G = (ci + 5) >> 3;
            if (G > gotG) {
                if (tid == 0) while (ld_acq(&g_done[G]) < NCONV) {}
                __syncthreads();
                gotG = G;
            }
            window(ci);
        }

        // acquire g_uh (all lora blocks published) before K-ext fills (f>=128)
        if (tid == 0) while (ld_acq(&g_flag) < NLORA) {}
        __syncthreads();

        for (int ci = 123; ci < NTI; ci += 3) window(ci);

        // epilogue: + bias -> y
        const int nb = bn * 128 + wn * 64;
        #pragma unroll
        for (int i = 0; i < 4; i++) {
            #pragma unroll
            for (int h = 0; h < 2; h++) {
                const int m = bm * 128 + wm * 64 + i * 16 + h * 8 + (lane >> 2);
                float* crow = C + (size_t)m * DOUT + nb + (lane & 3) * 2;
                #pragma unroll
                for (int j = 0; j < 8; j++) {
                    const float2 bv = *reinterpret_cast<const float2*>(
                        bias + nb + j * 8 + (lane & 3) * 2);
                    float2 v;
                    v.x = acc[i][j][h * 2 + 0] + bv.x;
                    v.y = acc[i][j][h * 2 + 1] + bv.y;
                    *reinterpret_cast<float2*>(crow + j * 8) = v;
                }
            }
        }
    }

    // ---- common exit: last block resets counters for the next graph replay ----
    __syncthreads();
    if (tid == 0) {
        __threadfence();
        const int ticket = atomicAdd(&g_exit, 1);
        if (ticket == GRID - 1) {
            #pragma unroll
            for (int i = 0; i < 16; i++) g_done[i] = 0;
            g_flag = 0;
            __threadfence();
            g_exit = 0;
        }
    }
}

// ---------------------------------------------------------------------------
extern "C" void kernel_launch(void* const* d_in, const int* in_sizes, int n_in,
                              void* d_out, int out_size)
{
    const float* x    = (const float*)d_in[0];
    const int*   t2s  = (const int*)  d_in[1];
    const float* w    = (const float*)d_in[2];
    const float* bias = (const float*)d_in[3];
    const float* lA   = (const float*)d_in[4];
    const float* lB   = (const float*)d_in[5];
    const float* scal = (const float*)d_in[6];
    float*       y    = (float*)d_out;

    constexpr int SMEM = 6 * (2048 + 2048) * 4;  // 96 KB (covers lora 48KB, conv 9.2KB)

    cudaFuncSetAttribute(fused_kernel, cudaFuncAttributeMaxDynamicSharedMemorySize, SMEM);

    fused_kernel<<<GRID, 128, SMEM>>>(x, w, lA, lB, t2s, scal, y, bias);
}

// round 14
// speedup vs baseline: 1.2634x; 1.2634x over previous
#include <cuda_runtime.h>
#include <cuda_fp16.h>
#include <cstdint>

// ---------------------------------------------------------------------------
// LoRARowParallelLinear, mma.sync fp16 m16n8k16 (compute_103-safe).
//   conv:  x -> fp16 A-frags, W/lora_A -> fp16 B-frags, Bcat; zeroes g_flag.
//   fused: blocks [0,128)   = lora GEMM u = mask*scal*(x @ lora_A^T) -> g_uh,
//                             then release g_flag.
//          blocks [128,2176)= main GEMM y = x@W^T + u@Bcat^T (K-ext) + bias;
//                             acquire-spin on g_flag just before the K-ext
//                             window (ci=123), ~93% into the mainloop.
//   main config: CTA 128x128, 4 warps (64x64 warp tile), 6 stages, occ 2,
//   barrier every 3 iterations, .cg (L2-only) staging, fill-before-wait on
//   window sub-iterations 2/3 (cpwait<3> preserves the completion guarantee).
// ---------------------------------------------------------------------------

#define DEVINL static __device__ __forceinline__

namespace {
constexpr int TOK = 8192, DIN = 4096, DOUT = 4096;
constexpr int KB16 = DIN / 16;   // 256 k16-blocks
constexpr int NTI  = 132;        // 128 main BK32 iters + 4 K-ext iters (= 44*3)
}

// scratch (allocation-free __device__ globals)
__device__ __align__(128) uint32_t g_xh  [(TOK / 16) * KB16 * 128];  // 67 MB
__device__ __align__(128) uint32_t g_wh  [(DOUT / 8) * KB16 * 64];   // 33.5 MB
__device__ __align__(128) uint32_t g_lah [16 * KB16 * 64];           // 1 MB
__device__ __align__(128) uint32_t g_bcat[(DOUT / 8) * 8 * 64];      // 1 MB
__device__ __align__(128) uint32_t g_uh  [(TOK / 16) * 8 * 128];     // 2 MB
__device__ int g_flag;

DEVINL uint32_t h2pack(float lo, float hi) {
    __half2 h = __float22half2_rn(make_float2(lo, hi));
    return *reinterpret_cast<uint32_t*>(&h);
}

DEVINL void mma_f16(float& d0, float& d1, float& d2, float& d3,
                    uint32_t a0, uint32_t a1, uint32_t a2, uint32_t a3,
                    uint32_t b0, uint32_t b1)
{
    asm volatile(
        "mma.sync.aligned.m16n8k16.row.col.f32.f16.f16.f32 "
        "{%0,%1,%2,%3},{%4,%5,%6,%7},{%8,%9},{%0,%1,%2,%3};"
        : "+f"(d0), "+f"(d1), "+f"(d2), "+f"(d3)
        : "r"(a0), "r"(a1), "r"(a2), "r"(a3), "r"(b0), "r"(b1));
}

DEVINL void cpa16(const uint32_t* smem_dst, const void* gsrc) {
    uint32_t s = (uint32_t)__cvta_generic_to_shared(smem_dst);
    asm volatile("cp.async.cg.shared.global [%0], [%1], 16;" :: "r"(s), "l"(gsrc));
}
DEVINL void cpcommit() { asm volatile("cp.async.commit_group;"); }
template <int N> DEVINL void cpwait() { asm volatile("cp.async.wait_group %0;" :: "n"(N)); }

// ---------------------------------------------------------------------------
// conv: fp32 -> packed fp16 frag-major, staged through smem. Zeroes g_flag.
// ---------------------------------------------------------------------------
__global__ void __launch_bounds__(256) conv_kernel(
    const float* __restrict__ x, const float* __restrict__ w,
    const float* __restrict__ la, const float* __restrict__ lb)
{
    if (blockIdx.x == 0 && threadIdx.x == 0) g_flag = 0;

    __shared__ float st[8][16 * 36];
    const int tid  = threadIdx.x;
    const int lane = tid & 31, warp = tid >> 5;
    const int gwarp = blockIdx.x * 8 + warp;
    const int nwarp = gridDim.x * 8;
    float* s = st[warp];
    const int g  = lane >> 2;
    const int k0 = (lane & 3) * 2;

    // x -> g_xh (A-frag). Superblock = 16 rows x 32 cols (2 k-blocks).
    {
        const int r = lane >> 1, coff = (lane & 1) * 16;
        for (int sb = gwarp; sb < 512 * 128; sb += nwarp) {
            const int mt = sb >> 7, kt2 = sb & 127;
            const float* base = x + (size_t)(mt * 16) * DIN + kt2 * 32;
            #pragma unroll
            for (int q = 0; q < 4; q++)
                *reinterpret_cast<float4*>(s + r * 36 + coff + q * 4) =
                    *reinterpret_cast<const float4*>(base + (size_t)r * DIN + coff + q * 4);
            __syncwarp();
            #pragma unroll
            for (int kb = 0; kb < 2; kb++) {
                const int K = kb * 16;
                uint4 v;
                v.x = h2pack(s[g * 36 + K + k0],           s[g * 36 + K + k0 + 1]);
                v.y = h2pack(s[(g + 8) * 36 + K + k0],     s[(g + 8) * 36 + K + k0 + 1]);
                v.z = h2pack(s[g * 36 + K + k0 + 8],       s[g * 36 + K + k0 + 9]);
                v.w = h2pack(s[(g + 8) * 36 + K + k0 + 8], s[(g + 8) * 36 + K + k0 + 9]);
                *reinterpret_cast<uint4*>(
                    g_xh + ((size_t)mt * KB16 + kt2 * 2 + kb) * 128 + lane * 4) = v;
            }
            __syncwarp();
        }
    }

    // w -> g_wh (B-frag). Superblock = 8 rows x 32 cols (2 k-blocks).
    {
        const int r = lane >> 2, coff = (lane & 3) * 8;
        for (int sb = gwarp; sb < 512 * 128; sb += nwarp) {
            const int nt = sb >> 7, kt2 = sb & 127;
            const float* base = w + (size_t)(nt * 8) * DIN + kt2 * 32;
            #pragma unroll
            for (int q = 0; q < 2; q++)
                *reinterpret_cast<float4*>(s + r * 36 + coff + q * 4) =
                    *reinterpret_cast<const float4*>(base + (size_t)r * DIN + coff + q * 4);
            __syncwarp();
            #pragma unroll
            for (int kb = 0; kb < 2; kb++) {
                const int K = kb * 16;
                uint2 v;
                v.x = h2pack(s[g * 36 + K + k0],     s[g * 36 + K + k0 + 1]);
                v.y = h2pack(s[g * 36 + K + k0 + 8], s[g * 36 + K + k0 + 9]);
                *reinterpret_cast<uint2*>(
                    g_wh + ((size_t)nt * KB16 + kt2 * 2 + kb) * 64 + lane * 2) = v;
            }
            __syncwarp();
        }
    }

    // lora_A -> g_lah (B-frag, 16 n-tiles)
    {
        const int r = lane >> 2, coff = (lane & 3) * 8;
        for (int sb = gwarp; sb < 16 * 128; sb += nwarp) {
            const int nt = sb >> 7, kt2 = sb & 127;
            const float* base = la + (size_t)(nt * 8) * DIN + kt2 * 32;
            #pragma unroll
            for (int q = 0; q < 2; q++)
                *reinterpret_cast<float4*>(s + r * 36 + coff + q * 4) =
                    *reinterpret_cast<const float4*>(base + (size_t)r * DIN + coff + q * 4);
            __syncwarp();
            #pragma unroll
            for (int kb = 0; kb < 2; kb++) {
                const int K = kb * 16;
                uint2 v;
                v.x = h2pack(s[g * 36 + K + k0],     s[g * 36 + K + k0 + 1]);
                v.y = h2pack(s[g * 36 + K + k0 + 8], s[g * 36 + K + k0 + 9]);
                *reinterpret_cast<uint2*>(
                    g_lah + ((size_t)nt * KB16 + kt2 * 2 + kb) * 64 + lane * 2) = v;
            }
            __syncwarp();
        }
    }

    // lora_B [8][DOUT][16] -> g_bcat (B-frag): Bcat[n][s*16+r] = lB[s][n][r]
    const int nth = gridDim.x * blockDim.x;
    const int gt  = blockIdx.x * 256 + tid;
    for (int i = gt; i < DOUT * 64; i += nth) {
        const int n = i >> 6, p = i & 63;
        const int kc = p * 2;
        const int sl = kc >> 4, rr = kc & 15;
        const float f0 = lb[(size_t)sl * DOUT * 16 + n * 16 + rr];
        const float f1 = lb[(size_t)sl * DOUT * 16 + n * 16 + rr + 1];
        const int nt = n >> 3, gg = n & 7;
        const int kbb  = kc >> 4;
        const int lpos = gg * 4 + ((kc & 7) >> 1);
        const int word = lpos * 2 + ((kc >> 3) & 1);
        g_bcat[((size_t)nt * 8 + kbb) * 64 + word] = h2pack(f0, f1);
    }
}

// ---------------------------------------------------------------------------
// fused kernel: lora blocks [0,128) + main blocks [128,2176).
// ---------------------------------------------------------------------------
__global__ void __launch_bounds__(128, 2) gemm_fused(
    float* __restrict__ C, const float* __restrict__ bias,
    const int* __restrict__ t2s, const float* __restrict__ scal)
{
    extern __shared__ uint32_t sm[];
    const int tid = threadIdx.x, lane = tid & 31, warp = tid >> 5;
    const int wm = warp >> 1, wn = warp & 1;

    if (blockIdx.x < 128) {
        // -------- lora GEMM: u = mask*scal*(x @ lora_A^T) --------
        constexpr int A_ST = 1024, B_ST = 2048, STW = A_ST + B_ST;  // words
        const int bm = blockIdx.x;

        float acc[2][8][4];
        #pragma unroll
        for (int i = 0; i < 2; i++)
            #pragma unroll
            for (int j = 0; j < 8; j++)
                #pragma unroll
                for (int k = 0; k < 4; k++) acc[i][j][k] = 0.f;

        auto load_stage = [&](int f, int buf) {
            uint32_t* sA = sm + buf * STW;
            uint32_t* sB = sA + A_ST;
            #pragma unroll
            for (int q = tid; q < 256; q += 128) {
                const int mt = q >> 6, kb = (q >> 5) & 1, c = q & 31;
                cpa16(sA + (mt * 2 + kb) * 128 + c * 4,
                      g_xh + ((size_t)(bm * 4 + mt) * KB16 + f * 2 + kb) * 128 + c * 4);
            }
            #pragma unroll
            for (int q = tid; q < 512; q += 128) {
                const int nt = q >> 5, kb = (q >> 4) & 1, c = q & 15;
                cpa16(sB + (nt * 2 + kb) * 64 + c * 4,
                      g_lah + ((size_t)nt * KB16 + f * 2 + kb) * 64 + c * 4);
            }
        };

        load_stage(0, 0); cpcommit();
        load_stage(1, 1); cpcommit();
        load_stage(2, 2); cpcommit();

        for (int ci = 0; ci < 128; ci++) {
            cpwait<2>();
            __syncthreads();
            if (ci + 3 < 128) load_stage(ci + 3, (ci + 3) & 3);
            cpcommit();

            const uint32_t* sA = sm + (ci & 3) * STW;
            const uint32_t* sB = sA + A_ST;
            const uint32_t* aw = sA + (wm * 2) * 2 * 128 + lane * 4;
            const uint32_t* bw = sB + (wn * 8) * 2 * 64 + lane * 2;

            #pragma unroll
            for (int kb = 0; kb < 2; kb++) {
                uint4 a[2];
                a[0] = *reinterpret_cast<const uint4*>(aw + kb * 128);
                a[1] = *reinterpret_cast<const uint4*>(aw + (2 + kb) * 128);
                uint2 b[8];
                #pragma unroll
                for (int j = 0; j < 8; j++)
                    b[j] = *reinterpret_cast<const uint2*>(bw + (j * 2 + kb) * 64);
                #pragma unroll
                for (int i = 0; i < 2; i++)
                    #pragma unroll
                    for (int j = 0; j < 8; j++)
                        mma_f16(acc[i][j][0], acc[i][j][1], acc[i][j][2], acc[i][j][3],
                                a[i].x, a[i].y, a[i].z, a[i].w, b[j].x, b[j].y);
            }
        }

        // epilogue: mask*scale -> g_uh fp16 A-frag blocks
        #pragma unroll
        for (int i = 0; i < 2; i++) {
            const int mrow0 = bm * 64 + wm * 32 + i * 16 + (lane >> 2);
            const int slot0 = t2s[mrow0];
            const int slot1 = t2s[mrow0 + 8];
            const float sc0 = scal[slot0];
            const float sc1 = scal[slot1];
            const int mt = bm * 4 + wm * 2 + i;
            #pragma unroll
            for (int j = 0; j < 8; j += 2) {
                const int kbg = wn * 4 + (j >> 1);
                const int n0 = wn * 64 + j * 8 + (lane & 3) * 2;
                const int n1 = n0 + 8;
                const float m00 = ((n0 >> 4) == slot0) ? sc0 : 0.f;
                const float m01 = ((n0 >> 4) == slot1) ? sc1 : 0.f;
                const float m10 = ((n1 >> 4) == slot0) ? sc0 : 0.f;
                const float m11 = ((n1 >> 4) == slot1) ? sc1 : 0.f;
                uint4 v;
                v.x = h2pack(acc[i][j][0] * m00,     acc[i][j][1] * m00);
                v.y = h2pack(acc[i][j][2] * m01,     acc[i][j][3] * m01);
                v.z = h2pack(acc[i][j + 1][0] * m10, acc[i][j + 1][1] * m10);
                v.w = h2pack(acc[i][j + 1][2] * m11, acc[i][j + 1][3] * m11);
                *reinterpret_cast<uint4*>(g_uh + ((size_t)mt * 8 + kbg) * 128 + lane * 4) = v;
            }
        }

        // release: u slice visible, count this block done
        __threadfence();
        __syncthreads();
        if (tid == 0) atomicAdd(&g_flag, 1);
        return;
    }

    // -------- main GEMM --------
    constexpr int A_ST = 2048, B_ST = 2048, STW = A_ST + B_ST;  // words/stage
    const int mid = blockIdx.x - 128;
    const int bn = mid & 31, bm = mid >> 5;

    float acc[4][8][4];
    #pragma unroll
    for (int i = 0; i < 4; i++)
        #pragma unroll
        for (int j = 0; j < 8; j++)
            #pragma unroll
            for (int k = 0; k < 4; k++) acc[i][j][k] = 0.f;

    auto load_stage = [&](int f, int buf) {
        uint32_t* sA = sm + buf * STW;
        uint32_t* sB = sA + A_ST;
        #pragma unroll
        for (int q = tid; q < 512; q += 128) {
            const int mt = q >> 6, kb = (q >> 5) & 1, c = q & 31;
            const uint32_t* src = (f < 128)
                ? g_xh + ((size_t)(bm * 8 + mt) * KB16 + f * 2 + kb) * 128 + c * 4
                : g_uh + ((size_t)(bm * 8 + mt) * 8 + (f - 128) * 2 + kb) * 128 + c * 4;
            cpa16(sA + (mt * 2 + kb) * 128 + c * 4, src);
        }
        #pragma unroll
        for (int q = tid; q < 512; q += 128) {
            const int nt = q >> 5, kb = (q >> 4) & 1, c = q & 15;
            const uint32_t* src = (f < 128)
                ? g_wh   + ((size_t)(bn * 16 + nt) * KB16 + f * 2 + kb) * 64 + c * 4
                : g_bcat + ((size_t)(bn * 16 + nt) * 8 + (f - 128) * 2 + kb) * 64 + c * 4;
            cpa16(sB + (nt * 2 + kb) * 64 + c * 4, src);
        }
    };

    auto compute = [&](int ci) {
        const uint32_t* sA = sm + (ci % 6) * STW;
        const uint32_t* sB = sA + A_ST;
        const uint32_t* aw = sA + (wm * 4) * 2 * 128 + lane * 4;
        const uint32_t* bw = sB + (wn * 8) * 2 * 64 + lane * 2;
        #pragma unroll
        for (int kb = 0; kb < 2; kb++) {
            uint4 a[4];
            #pragma unroll
            for (int i = 0; i < 4; i++)
                a[i] = *reinterpret_cast<const uint4*>(aw + (i * 2 + kb) * 128);
            uint2 b[8];
            #pragma unroll
            for (int j = 0; j < 8; j++)
                b[j] = *reinterpret_cast<const uint2*>(bw + (j * 2 + kb) * 64);
            #pragma unroll
            for (int i = 0; i < 4; i++)
                #pragma unroll
                for (int j = 0; j < 8; j++)
                    mma_f16(acc[i][j][0], acc[i][j][1], acc[i][j][2], acc[i][j][3],
                            a[i].x, a[i].y, a[i].z, a[i].w, b[j].x, b[j].y);
        }
    };

    // Window of 3 iterations, one CTA barrier per window.
    // Sub-iters 2/3 issue the next fill BEFORE waiting: after committing
    // fill(ci+4), pending groups are {ci+1..ci+4}; cpwait<3> drains to 3
    // pending, i.e. fill(ci+1) — the stage compute(ci+1) reads — is done.
    auto window = [&](int ci) {
        cpwait<2>();
        __syncthreads();
        if (ci + 3 < NTI) load_stage(ci + 3, (ci + 3) % 6);
        cpcommit();
        compute(ci);
        if (ci + 4 < NTI) load_stage(ci + 4, (ci + 4) % 6);
        cpcommit();
        cpwait<3>();
        compute(ci + 1);
        if (ci + 5 < NTI) load_stage(ci + 5, (ci + 5) % 6);
        cpcommit();
        cpwait<3>();
        compute(ci + 2);
    };

    load_stage(0, 0); cpcommit();
    load_stage(1, 1); cpcommit();
    load_stage(2, 2); cpcommit();

    // windows 0..120: all fills f <= 125 (< 128), no g_uh dependency
    for (int ci = 0; ci < 123; ci += 3) window(ci);

    // acquire: all 128 lora blocks must have published g_uh before fills
    // of f >= 128 (first issued in window 123).
    if (tid == 0) {
        int v;
        do {
            asm volatile("ld.acquire.gpu.global.b32 %0, [%1];"
                         : "=r"(v) : "l"(&g_flag) : "memory");
        } while (v < 128);
    }
    __syncthreads();

    // windows 123, 126, 129 (fills f = 126..131)
    for (int ci = 123; ci < NTI; ci += 3) window(ci);

    // epilogue: + bias -> y
    const int nb = bn * 128 + wn * 64;
    #pragma unroll
    for (int i = 0; i < 4; i++) {
        #pragma unroll
        for (int h = 0; h < 2; h++) {
            const int m = bm * 128 + wm * 64 + i * 16 + h * 8 + (lane >> 2);
            float* crow = C + (size_t)m * DOUT + nb + (lane & 3) * 2;
            #pragma unroll
            for (int j = 0; j < 8; j++) {
                const float2 bv = *reinterpret_cast<const float2*>(
                    bias + nb + j * 8 + (lane & 3) * 2);
                float2 v;
                v.x = acc[i][j][h * 2 + 0] + bv.x;
                v.y = acc[i][j][h * 2 + 1] + bv.y;
                *reinterpret_cast<float2*>(crow + j * 8) = v;
            }
        }
    }
}

// ---------------------------------------------------------------------------
extern "C" void kernel_launch(void* const* d_in, const int* in_sizes, int n_in,
                              void* d_out, int out_size)
{
    const float* x    = (const float*)d_in[0];
    const int*   t2s  = (const int*)  d_in[1];
    const float* w    = (const float*)d_in[2];
    const float* bias = (const float*)d_in[3];
    const float* lA   = (const float*)d_in[4];
    const float* lB   = (const float*)d_in[5];
    const float* scal = (const float*)d_in[6];
    float*       y    = (float*)d_out;

    constexpr int SMEM1 = 6 * (2048 + 2048) * 4;  // 96 KB (covers lora's 48 KB)

    cudaFuncSetAttribute(gemm_fused, cudaFuncAttributeMaxDynamicSharedMemorySize, SMEM1);

    // 1) convert all operands to fp16 fragment-major scratch; reset flag
    conv_kernel<<<1184, 256>>>(x, w, lA, lB);
    // 2) fused: lora blocks (0..127) + main blocks (128..2175)
    gemm_fused<<<128 + 2048, 128, SMEM1>>>(y, bias, t2s, scal);
}